// round 16
// baseline (speedup 1.0000x reference)
#include <cuda_runtime.h>
#include <cuda_fp16.h>
#include <cstdint>

#define BB 8
#define NN 2048
#define DD 384
#define HH 6
#define DH 64
#define MMR (BB*NN)
#define QKV_N (3*DD)
#define QS   0.18033688f      // 0.125 * log2(e); shift-free softmax (cancels in norm)

// ---------------- device scratch (referenced ONLY in device code) ----------
__device__ __half gxh[MMR*DD];      // x (fp16)
__device__ __half gwqh[QKV_N*DD];   // w_qkv (fp16)
__device__ __half gwoh[DD*DD];      // w_out (fp16)
__device__ __half gqh[MMR*DD];      // [b,h,n,d], pre-scaled by QS
__device__ __half gkh[MMR*DD];      // [b,h,n,d]
__device__ __half gvh[MMR*DD];      // [b,h,n,d]
__device__ __half gah[MMR*DD];      // attn out [B*N, D]

// ---------------- helpers ----------------
__device__ __forceinline__ uint32_t s2u(const void* p){
    uint32_t a;
    asm("{ .reg .u64 t; cvta.to.shared.u64 t, %1; cvt.u32.u64 %0, t; }":"=r"(a):"l"(p));
    return a;
}
__device__ __forceinline__ uint32_t swz(uint32_t x){ return x ^ ((x>>3)&0x70); }
__device__ __forceinline__ void cp16(uint32_t d, const void* s){
    asm volatile("cp.async.cg.shared.global [%0], [%1], 16;"::"r"(d),"l"(s):"memory");
}
#define CPCOMMIT() asm volatile("cp.async.commit_group;":::"memory")
#define CPWAIT1()  asm volatile("cp.async.wait_group 1;":::"memory")
#define CPWAIT2()  asm volatile("cp.async.wait_group 2;":::"memory")

__device__ __forceinline__ void ldm4(uint32_t& r0,uint32_t& r1,uint32_t& r2,uint32_t& r3,uint32_t a){
    asm volatile("ldmatrix.sync.aligned.m8n8.x4.shared.b16 {%0,%1,%2,%3}, [%4];"
        :"=r"(r0),"=r"(r1),"=r"(r2),"=r"(r3):"r"(a));
}
__device__ __forceinline__ void ldm4t(uint32_t& r0,uint32_t& r1,uint32_t& r2,uint32_t& r3,uint32_t a){
    asm volatile("ldmatrix.sync.aligned.m8n8.x4.trans.shared.b16 {%0,%1,%2,%3}, [%4];"
        :"=r"(r0),"=r"(r1),"=r"(r2),"=r"(r3):"r"(a));
}
__device__ __forceinline__ void mma16816(float* c, uint32_t a0,uint32_t a1,uint32_t a2,uint32_t a3,
                                          uint32_t b0,uint32_t b1){
    asm volatile("mma.sync.aligned.m16n8k16.row.col.f32.f16.f16.f32 "
        "{%0,%1,%2,%3},{%4,%5,%6,%7},{%8,%9},{%0,%1,%2,%3};"
        :"+f"(c[0]),"+f"(c[1]),"+f"(c[2]),"+f"(c[3])
        :"r"(a0),"r"(a1),"r"(a2),"r"(a3),"r"(b0),"r"(b1));
}
__device__ __forceinline__ uint32_t cvt2h(float hi, float lo){
    uint32_t r; asm("cvt.rn.f16x2.f32 %0, %1, %2;" : "=r"(r) : "f"(hi), "f"(lo)); return r;
}
__device__ __forceinline__ uint32_t hex2(uint32_t x){
    uint32_t r; asm("ex2.approx.f16x2 %0, %1;" : "=r"(r) : "r"(x)); return r;
}
__device__ __forceinline__ uint32_t pk(__half a, __half b){
    __half2 t = __halves2half2(a, b);
    return *reinterpret_cast<uint32_t*>(&t);
}

// ---- fp32 -> fp16 input conversions (2 elems/thread) ----------------------
__global__ void splitX(const float* __restrict__ s){
    int i = blockIdx.x*256 + threadIdx.x;
    float2 v = ((const float2*)s)[i];
    ((uint32_t*)gxh)[i] = pk(__float2half_rn(v.x), __float2half_rn(v.y));
}
__global__ void splitWQ(const float* __restrict__ s){
    int i = blockIdx.x*256 + threadIdx.x;
    float2 v = ((const float2*)s)[i];
    ((uint32_t*)gwqh)[i] = pk(__float2half_rn(v.x), __float2half_rn(v.y));
}
__global__ void splitWO(const float* __restrict__ s){
    int i = blockIdx.x*256 + threadIdx.x;
    float2 v = ((const float2*)s)[i];
    ((uint32_t*)gwoh)[i] = pk(__float2half_rn(v.x), __float2half_rn(v.y));
}

// ---------------------------------------------------------------------------
// Projection GEMM body: 1-term fp16, 128x128 tile, 8 warps (64x32 each),
// K-chunk 64, double-buffered 32KB stages, 2 CTAs/SM.  (Unchanged from R15.)
// ---------------------------------------------------------------------------
#define P_SMEM 65536

#define PROJ_BODY(AHP, BHP)                                                   \
    extern __shared__ char smc[];                                             \
    const uint32_t sb = s2u(smc);                                             \
    const int tid = threadIdx.x, lane = tid&31, wid = tid>>5;                 \
    const int wm = wid>>2, wn = wid&3;                                        \
    const int n0 = blockIdx.x*128, m0 = blockIdx.y*128;                       \
    float acc[4][4][4] = {};                                                  \
    auto loadP = [&](int c){                                                  \
        uint32_t st = sb + (uint32_t)(c&1)*32768u;                            \
        for (int i = tid; i < 1024; i += 256){                                \
            int r = i>>3, cc = i&7;                                           \
            uint32_t o = swz((uint32_t)(r*128 + cc*16));                      \
            cp16(st+o,       AHP + (size_t)(m0+r)*DD + c*64 + cc*8);          \
            cp16(st+16384+o, BHP + (size_t)(n0+r)*DD + c*64 + cc*8);          \
        }                                                                     \
        CPCOMMIT();                                                           \
    };                                                                        \
    loadP(0); loadP(1);                                                       \
    for (int c = 0; c < 6; c++){                                              \
        CPWAIT1(); __syncthreads();                                           \
        uint32_t st = sb + (uint32_t)(c&1)*32768u;                            \
        _Pragma("unroll")                                                     \
        for (int s = 0; s < 4; s++){                                          \
            uint32_t af[4][4];                                                \
            _Pragma("unroll")                                                 \
            for (int mt = 0; mt < 4; mt++){                                   \
                int arow = wm*64 + mt*16 + (lane&15);                         \
                uint32_t ao = swz((uint32_t)(arow*128) +                      \
                                  (uint32_t)(s*32 + ((lane>>4)&1)*16));       \
                ldm4(af[mt][0],af[mt][1],af[mt][2],af[mt][3], st+ao);         \
            }                                                                 \
            _Pragma("unroll")                                                 \
            for (int np = 0; np < 2; np++){                                   \
                int brow = wn*32 + np*16 + (lane&7) + ((lane&16)?8:0);        \
                uint32_t bo_ = swz((uint32_t)(brow*128) +                     \
                                   (uint32_t)(s*32 + ((lane&8)?16:0)));       \
                uint32_t b0,b1,b2,b3;                                         \
                ldm4(b0,b1,b2,b3, st+16384+bo_);                              \
                _Pragma("unroll")                                             \
                for (int mt = 0; mt < 4; mt++){                               \
                    mma16816(acc[mt][2*np],   af[mt][0],af[mt][1],af[mt][2],af[mt][3], b0,b1); \
                    mma16816(acc[mt][2*np+1], af[mt][0],af[mt][1],af[mt][2],af[mt][3], b2,b3); \
                }                                                             \
            }                                                                 \
        }                                                                     \
        __syncthreads();                                                      \
        if (c+2 < 6) loadP(c+2); else CPCOMMIT();                             \
    }

// QKV projection with fused scatter epilogue (q/k/v fp16, all [b,h,n,d])
__global__ __launch_bounds__(256,2) void qkv_tc(const float* __restrict__ bias)
{
    PROJ_BODY(gxh, gwqh)

    const int region = n0/384;
#pragma unroll
    for (int mt = 0; mt < 4; mt++){
#pragma unroll
        for (int nt = 0; nt < 4; nt++){
            int e = n0 + wn*32 + nt*8 + (lane&3)*2;
            float bs0 = bias[e], bs1 = bias[e+1];
            int le = e - region*384;
            int h = le >> 6, d = le & 63;
#pragma unroll
            for (int hf = 0; hf < 2; hf++){
                int m = m0 + wm*64 + mt*16 + (lane>>2) + hf*8;
                int b = m >> 11, n = m & (NN-1);
                float v0 = acc[mt][nt][hf*2]   + bs0;
                float v1 = acc[mt][nt][hf*2+1] + bs1;
                if (region == 0){ v0 *= QS; v1 *= QS; }
                size_t off = ((size_t)((b*HH+h)*NN) + n)*DH + d;
                __half* dst = (region == 0) ? gqh : ((region == 1) ? gkh : gvh);
                *(uint32_t*)(dst+off) = pk(__float2half_rn(v0), __float2half_rn(v1));
            }
        }
    }
}

// Out projection, fp32 output
__global__ __launch_bounds__(256,2) void out_tc(const float* __restrict__ bias,
                                                float* __restrict__ outp)
{
    PROJ_BODY(gah, gwoh)

#pragma unroll
    for (int mt = 0; mt < 4; mt++){
#pragma unroll
        for (int nt = 0; nt < 4; nt++){
            int e = n0 + wn*32 + nt*8 + (lane&3)*2;
            float bs0 = bias[e], bs1 = bias[e+1];
#pragma unroll
            for (int hf = 0; hf < 2; hf++){
                int m = m0 + wm*64 + mt*16 + (lane>>2) + hf*8;
                *(float2*)(outp + (size_t)m*DD + e) =
                    make_float2(acc[mt][nt][hf*2] + bs0, acc[mt][nt][hf*2+1] + bs1);
            }
        }
    }
}

// ---------------------------------------------------------------------------
// Tensor-core attention, re-tiled for fragment reuse:
// warp grid = 4 row-tiles x 2 key-halves; each warp: 32 q-rows x 32 keys/stage.
// K/V B-fragments reused across 2 A-tiles -> LDSM/stage 36 -> 24.
// Cross-warp (key-half) O/li reduction via smem at the end.
// SMEM (80KB): stage u @ (u&3)*16K: K 0..8K | V 8K..16K.  Q @64K.
// ---------------------------------------------------------------------------
#define A_SMEM 81920

__global__ __launch_bounds__(256,2)
void attn_tc()
{
    extern __shared__ char smc[];
    const uint32_t sb = s2u(smc);
    const int tid = threadIdx.x, lane = tid&31, wid = tid>>5;
    const int wr = wid&3, wk = wid>>2;        // row-tile, key-half
    const int i0 = blockIdx.x*128, bh = blockIdx.y;
    const size_t bo = (size_t)bh*NN*DH;

    // Q load (joins group 0 with KV stage 0)
    for (int i = tid; i < 1024; i += 256){
        int r = i>>3, cc = i&7;
        cp16(sb+65536+swz((uint32_t)(r*128 + cc*16)),
             gqh + bo + (size_t)(i0+r)*DH + cc*8);
    }
    auto loadKV = [&](int u){   // u = 64-key tile index, 0..31
        uint32_t st = sb + (uint32_t)(u&3)*16384u;
        for (int i = tid; i < 512; i += 256){
            int r = i>>3, cc = i&7;
            cp16(st+swz((uint32_t)(r*128 + cc*16)),
                 gkh + bo + (size_t)(u*64 + r)*DH + cc*8);
        }
        for (int i = tid; i < 512; i += 256){
            int r = i>>3, cc = i&7;
            cp16(st+8192+swz((uint32_t)(r*128 + cc*16)),
                 gvh + bo + (size_t)(u*64 + r)*DH + cc*8);
        }
        CPCOMMIT();
    };
    loadKV(0); loadKV(1); loadKV(2);   // 3 groups in flight

    float oacc[2][8][4] = {};
    float liacc[2][4] = {};
    const uint32_t ones = (lane < 4) ? 0x3C003C00u : 0u;

    for (int t = 0; t < 32; t++){
        CPWAIT2();
        __syncthreads();
        if (t+3 < 32) loadKV(t+3); else CPCOMMIT();
        uint32_t st = sb + (uint32_t)(t&3)*16384u;

        // ---- S = Q K^T : 32 rows x 32 keys per warp ----
        float sacc[2][4][4] = {};
#pragma unroll
        for (int s = 0; s < 4; s++){
            uint32_t qf[2][4];
#pragma unroll
            for (int mt = 0; mt < 2; mt++){
                int qrow = wr*32 + mt*16 + (lane&15);
                uint32_t qo = swz((uint32_t)(qrow*128) +
                                  (uint32_t)(s*32 + ((lane>>4)&1)*16));
                ldm4(qf[mt][0],qf[mt][1],qf[mt][2],qf[mt][3], sb+65536+qo);
            }
#pragma unroll
            for (int nb = 0; nb < 2; nb++){
                int krow = wk*32 + nb*16 + (lane&7) + ((lane&16)?8:0);
                uint32_t ko = swz((uint32_t)(krow*128) +
                                  (uint32_t)(s*32 + ((lane&8)?16:0)));
                uint32_t b0,b1,b2,b3;
                ldm4(b0,b1,b2,b3, st+ko);
#pragma unroll
                for (int mt = 0; mt < 2; mt++){
                    mma16816(sacc[mt][nb*2],   qf[mt][0],qf[mt][1],qf[mt][2],qf[mt][3], b0,b1);
                    mma16816(sacc[mt][nb*2+1], qf[mt][0],qf[mt][1],qf[mt][2],qf[mt][3], b2,b3);
                }
            }
        }

        // ---- softmax (shift-free) + li-MMA + PV ----
#pragma unroll
        for (int jk = 0; jk < 2; jk++){
            uint32_t pa[2][4];
#pragma unroll
            for (int mt = 0; mt < 2; mt++){
                pa[mt][0] = hex2(cvt2h(sacc[mt][jk*2][1],   sacc[mt][jk*2][0]));
                pa[mt][1] = hex2(cvt2h(sacc[mt][jk*2][3],   sacc[mt][jk*2][2]));
                pa[mt][2] = hex2(cvt2h(sacc[mt][jk*2+1][1], sacc[mt][jk*2+1][0]));
                pa[mt][3] = hex2(cvt2h(sacc[mt][jk*2+1][3], sacc[mt][jk*2+1][2]));
                mma16816(liacc[mt], pa[mt][0],pa[mt][1],pa[mt][2],pa[mt][3], ones, ones);
            }
#pragma unroll
            for (int dp = 0; dp < 4; dp++){
                int krow = wk*32 + jk*16 + (lane&7) + ((lane&8)?8:0);
                uint32_t o = swz((uint32_t)(krow*128) +
                                 (uint32_t)(dp*32 + ((lane&16)?16:0)));
                uint32_t v0,v1,v2,v3;
                ldm4t(v0,v1,v2,v3, st+8192+o);
#pragma unroll
                for (int mt = 0; mt < 2; mt++){
                    mma16816(oacc[mt][dp*2],   pa[mt][0],pa[mt][1],pa[mt][2],pa[mt][3], v0,v1);
                    mma16816(oacc[mt][dp*2+1], pa[mt][0],pa[mt][1],pa[mt][2],pa[mt][3], v2,v3);
                }
            }
        }
    }

    // ---- cross-warp reduction (key-half 1 -> key-half 0) via smem ----
    // red: 128 rows x 64 cols fp32, stride 66 (pad) @ sb; lis @ sb+34816.
    // Safe to reuse slots 0-2: their last reads finished >=2 barriers ago.
    float* red = (float*)smc;
    float* lis = (float*)(smc + 34816);
    if (wk == 1){
#pragma unroll
        for (int mt = 0; mt < 2; mt++){
            int row0 = wr*32 + mt*16 + (lane>>2);
#pragma unroll
            for (int nn = 0; nn < 8; nn++){
                int col = nn*8 + (lane&3)*2;
                *(float2*)&red[row0*66 + col]     = make_float2(oacc[mt][nn][0], oacc[mt][nn][1]);
                *(float2*)&red[(row0+8)*66 + col] = make_float2(oacc[mt][nn][2], oacc[mt][nn][3]);
            }
            if ((lane&3) == 0){
                lis[row0]   = liacc[mt][0];
                lis[row0+8] = liacc[mt][2];
            }
        }
    }
    __syncthreads();
    if (wk == 0){
        const int b = bh/HH, h = bh%HH;
#pragma unroll
        for (int mt = 0; mt < 2; mt++){
            int row0 = wr*32 + mt*16 + (lane>>2);
            float inv0 = 1.0f/(__shfl_sync(0xffffffffu, liacc[mt][0], lane & ~3) + lis[row0]);
            float inv1 = 1.0f/(__shfl_sync(0xffffffffu, liacc[mt][2], lane & ~3) + lis[row0+8]);
            size_t base0 = ((size_t)(b*NN + i0 + row0))*DD + h*DH;
            size_t base1 = ((size_t)(b*NN + i0 + row0 + 8))*DD + h*DH;
#pragma unroll
            for (int nn = 0; nn < 8; nn++){
                int col = nn*8 + (lane&3)*2;
                float2 r0 = *(float2*)&red[row0*66 + col];
                float2 r1 = *(float2*)&red[(row0+8)*66 + col];
                *(uint32_t*)(gah + base0 + col) =
                    pk(__float2half_rn((oacc[mt][nn][0]+r0.x)*inv0),
                       __float2half_rn((oacc[mt][nn][1]+r0.y)*inv0));
                *(uint32_t*)(gah + base1 + col) =
                    pk(__float2half_rn((oacc[mt][nn][2]+r1.x)*inv1),
                       __float2half_rn((oacc[mt][nn][3]+r1.y)*inv1));
            }
        }
    }
}

// ---------------------------------------------------------------------------
extern "C" void kernel_launch(void* const* d_in, const int* in_sizes, int n_in,
                              void* d_out, int out_size)
{
    const float* x     = (const float*)d_in[0];
    const float* w_qkv = (const float*)d_in[1];
    const float* b_qkv = (const float*)d_in[2];
    const float* w_out = (const float*)d_in[3];
    const float* b_out = (const float*)d_in[4];
    float* out = (float*)d_out;

    cudaFuncSetAttribute(qkv_tc,  cudaFuncAttributeMaxDynamicSharedMemorySize, P_SMEM);
    cudaFuncSetAttribute(out_tc,  cudaFuncAttributeMaxDynamicSharedMemorySize, P_SMEM);
    cudaFuncSetAttribute(attn_tc, cudaFuncAttributeMaxDynamicSharedMemorySize, A_SMEM);

    splitX <<<(MMR*DD/2)/256,   256>>>(x);
    splitWQ<<<(QKV_N*DD/2)/256, 256>>>(w_qkv);
    splitWO<<<(DD*DD/2)/256,    256>>>(w_out);

    qkv_tc<<<dim3(QKV_N/128, MMR/128), 256, P_SMEM>>>(b_qkv);
    attn_tc<<<dim3(NN/128, BB*HH), 256, A_SMEM>>>();
    out_tc<<<dim3(DD/128, MMR/128), 256, P_SMEM>>>(b_out, out);
}

// round 17
// speedup vs baseline: 1.1326x; 1.1326x over previous
#include <cuda_runtime.h>
#include <cuda_fp16.h>
#include <cstdint>

#define BB 8
#define NN 2048
#define DD 384
#define HH 6
#define DH 64
#define MMR (BB*NN)
#define QKV_N (3*DD)
#define QS   0.18033688f      // 0.125 * log2(e); shift-free softmax (cancels in norm)

// ---------------- device scratch (referenced ONLY in device code) ----------
__device__ __half gxh[MMR*DD];      // x (fp16)
__device__ __half gwqh[QKV_N*DD];   // w_qkv (fp16)
__device__ __half gwoh[DD*DD];      // w_out (fp16)
__device__ __half gqh[MMR*DD];      // [b,h,n,d], pre-scaled by QS
__device__ __half gkh[MMR*DD];      // [b,h,n,d]
__device__ __half gvh[MMR*DD];      // [b,h,n,d]
__device__ __half gah[MMR*DD];      // attn out [B*N, D]

// ---------------- helpers ----------------
__device__ __forceinline__ uint32_t s2u(const void* p){
    uint32_t a;
    asm("{ .reg .u64 t; cvta.to.shared.u64 t, %1; cvt.u32.u64 %0, t; }":"=r"(a):"l"(p));
    return a;
}
__device__ __forceinline__ uint32_t swz(uint32_t x){ return x ^ ((x>>3)&0x70); }
__device__ __forceinline__ void cp16(uint32_t d, const void* s){
    asm volatile("cp.async.cg.shared.global [%0], [%1], 16;"::"r"(d),"l"(s):"memory");
}
#define CPCOMMIT() asm volatile("cp.async.commit_group;":::"memory")
#define CPWAIT1()  asm volatile("cp.async.wait_group 1;":::"memory")
#define CPWAIT2()  asm volatile("cp.async.wait_group 2;":::"memory")

__device__ __forceinline__ void ldm4(uint32_t& r0,uint32_t& r1,uint32_t& r2,uint32_t& r3,uint32_t a){
    asm volatile("ldmatrix.sync.aligned.m8n8.x4.shared.b16 {%0,%1,%2,%3}, [%4];"
        :"=r"(r0),"=r"(r1),"=r"(r2),"=r"(r3):"r"(a));
}
__device__ __forceinline__ void ldm4t(uint32_t& r0,uint32_t& r1,uint32_t& r2,uint32_t& r3,uint32_t a){
    asm volatile("ldmatrix.sync.aligned.m8n8.x4.trans.shared.b16 {%0,%1,%2,%3}, [%4];"
        :"=r"(r0),"=r"(r1),"=r"(r2),"=r"(r3):"r"(a));
}
__device__ __forceinline__ void mma16816(float* c, uint32_t a0,uint32_t a1,uint32_t a2,uint32_t a3,
                                          uint32_t b0,uint32_t b1){
    asm volatile("mma.sync.aligned.m16n8k16.row.col.f32.f16.f16.f32 "
        "{%0,%1,%2,%3},{%4,%5,%6,%7},{%8,%9},{%0,%1,%2,%3};"
        :"+f"(c[0]),"+f"(c[1]),"+f"(c[2]),"+f"(c[3])
        :"r"(a0),"r"(a1),"r"(a2),"r"(a3),"r"(b0),"r"(b1));
}
__device__ __forceinline__ uint32_t cvt2h(float hi, float lo){
    uint32_t r; asm("cvt.rn.f16x2.f32 %0, %1, %2;" : "=r"(r) : "f"(hi), "f"(lo)); return r;
}
__device__ __forceinline__ uint32_t hex2(uint32_t x){
    uint32_t r; asm("ex2.approx.f16x2 %0, %1;" : "=r"(r) : "r"(x)); return r;
}
__device__ __forceinline__ uint32_t pk(__half a, __half b){
    __half2 t = __halves2half2(a, b);
    return *reinterpret_cast<uint32_t*>(&t);
}

// ---- fused fp32 -> fp16 conversions (one launch for x, w_qkv, w_out) ------
#define NX2  (MMR*DD/2)
#define NWQ2 (QKV_N*DD/2)
#define NWO2 (DD*DD/2)
__global__ void splitAll(const float* __restrict__ x, const float* __restrict__ wq,
                         const float* __restrict__ wo){
    int i = blockIdx.x*256 + threadIdx.x;
    if (i < NX2){
        float2 v = ((const float2*)x)[i];
        ((uint32_t*)gxh)[i] = pk(__float2half_rn(v.x), __float2half_rn(v.y));
    }
    if (i < NWQ2){
        float2 v = ((const float2*)wq)[i];
        ((uint32_t*)gwqh)[i] = pk(__float2half_rn(v.x), __float2half_rn(v.y));
    }
    if (i < NWO2){
        float2 v = ((const float2*)wo)[i];
        ((uint32_t*)gwoh)[i] = pk(__float2half_rn(v.x), __float2half_rn(v.y));
    }
}

// ---------------------------------------------------------------------------
// Projection GEMM body: 1-term fp16, 128x128 tile, 8 warps (64x32 each),
// K-chunk 64, double-buffered 32KB stages, 2 CTAs/SM.
// ---------------------------------------------------------------------------
#define P_SMEM 65536

#define PROJ_BODY(AHP, BHP)                                                   \
    extern __shared__ char smc[];                                             \
    const uint32_t sb = s2u(smc);                                             \
    const int tid = threadIdx.x, lane = tid&31, wid = tid>>5;                 \
    const int wm = wid>>2, wn = wid&3;                                        \
    const int n0 = blockIdx.x*128, m0 = blockIdx.y*128;                       \
    float acc[4][4][4] = {};                                                  \
    auto loadP = [&](int c){                                                  \
        uint32_t st = sb + (uint32_t)(c&1)*32768u;                            \
        for (int i = tid; i < 1024; i += 256){                                \
            int r = i>>3, cc = i&7;                                           \
            uint32_t o = swz((uint32_t)(r*128 + cc*16));                      \
            cp16(st+o,       AHP + (size_t)(m0+r)*DD + c*64 + cc*8);          \
            cp16(st+16384+o, BHP + (size_t)(n0+r)*DD + c*64 + cc*8);          \
        }                                                                     \
        CPCOMMIT();                                                           \
    };                                                                        \
    loadP(0); loadP(1);                                                       \
    for (int c = 0; c < 6; c++){                                              \
        CPWAIT1(); __syncthreads();                                           \
        uint32_t st = sb + (uint32_t)(c&1)*32768u;                            \
        _Pragma("unroll")                                                     \
        for (int s = 0; s < 4; s++){                                          \
            uint32_t af[4][4];                                                \
            _Pragma("unroll")                                                 \
            for (int mt = 0; mt < 4; mt++){                                   \
                int arow = wm*64 + mt*16 + (lane&15);                         \
                uint32_t ao = swz((uint32_t)(arow*128) +                      \
                                  (uint32_t)(s*32 + ((lane>>4)&1)*16));       \
                ldm4(af[mt][0],af[mt][1],af[mt][2],af[mt][3], st+ao);         \
            }                                                                 \
            _Pragma("unroll")                                                 \
            for (int np = 0; np < 2; np++){                                   \
                int brow = wn*32 + np*16 + (lane&7) + ((lane&16)?8:0);        \
                uint32_t bo_ = swz((uint32_t)(brow*128) +                     \
                                   (uint32_t)(s*32 + ((lane&8)?16:0)));       \
                uint32_t b0,b1,b2,b3;                                         \
                ldm4(b0,b1,b2,b3, st+16384+bo_);                              \
                _Pragma("unroll")                                             \
                for (int mt = 0; mt < 4; mt++){                               \
                    mma16816(acc[mt][2*np],   af[mt][0],af[mt][1],af[mt][2],af[mt][3], b0,b1); \
                    mma16816(acc[mt][2*np+1], af[mt][0],af[mt][1],af[mt][2],af[mt][3], b2,b3); \
                }                                                             \
            }                                                                 \
        }                                                                     \
        __syncthreads();                                                      \
        if (c+2 < 6) loadP(c+2); else CPCOMMIT();                             \
    }

// QKV projection with fused scatter epilogue (q/k/v fp16, all [b,h,n,d])
__global__ __launch_bounds__(256,2) void qkv_tc(const float* __restrict__ bias)
{
    PROJ_BODY(gxh, gwqh)

    const int region = n0/384;
#pragma unroll
    for (int mt = 0; mt < 4; mt++){
#pragma unroll
        for (int nt = 0; nt < 4; nt++){
            int e = n0 + wn*32 + nt*8 + (lane&3)*2;
            float bs0 = bias[e], bs1 = bias[e+1];
            int le = e - region*384;
            int h = le >> 6, d = le & 63;
#pragma unroll
            for (int hf = 0; hf < 2; hf++){
                int m = m0 + wm*64 + mt*16 + (lane>>2) + hf*8;
                int b = m >> 11, n = m & (NN-1);
                float v0 = acc[mt][nt][hf*2]   + bs0;
                float v1 = acc[mt][nt][hf*2+1] + bs1;
                if (region == 0){ v0 *= QS; v1 *= QS; }
                size_t off = ((size_t)((b*HH+h)*NN) + n)*DH + d;
                __half* dst = (region == 0) ? gqh : ((region == 1) ? gkh : gvh);
                *(uint32_t*)(dst+off) = pk(__float2half_rn(v0), __float2half_rn(v1));
            }
        }
    }
}

// Out projection, fp32 output
__global__ __launch_bounds__(256,2) void out_tc(const float* __restrict__ bias,
                                                float* __restrict__ outp)
{
    PROJ_BODY(gah, gwoh)

#pragma unroll
    for (int mt = 0; mt < 4; mt++){
#pragma unroll
        for (int nt = 0; nt < 4; nt++){
            int e = n0 + wn*32 + nt*8 + (lane&3)*2;
            float bs0 = bias[e], bs1 = bias[e+1];
#pragma unroll
            for (int hf = 0; hf < 2; hf++){
                int m = m0 + wm*64 + mt*16 + (lane>>2) + hf*8;
                *(float2*)(outp + (size_t)m*DD + e) =
                    make_float2(acc[mt][nt][hf*2] + bs0, acc[mt][nt][hf*2+1] + bs1);
            }
        }
    }
}

// ---------------------------------------------------------------------------
// Tensor-core attention (R15 structure + persistent Q fragments):
// warp = 16 q-rows x 64 keys/stage; Q frags loaded once at t=0.
// SMEM (80KB): stage u @ (u&3)*16K: K 0..8K | V 8K..16K.  Q @64K.
// 4-deep stages, 2 CTAs/SM, one barrier per stage.
// ---------------------------------------------------------------------------
#define A_SMEM 81920

__global__ __launch_bounds__(256,2)
void attn_tc()
{
    extern __shared__ char smc[];
    const uint32_t sb = s2u(smc);
    const int tid = threadIdx.x, lane = tid&31, wid = tid>>5;
    const int i0 = blockIdx.x*128, bh = blockIdx.y;
    const size_t bo = (size_t)bh*NN*DH;

    // Q load (joins group 0 with KV stage 0)
    for (int i = tid; i < 1024; i += 256){
        int r = i>>3, cc = i&7;
        cp16(sb+65536+swz((uint32_t)(r*128 + cc*16)),
             gqh + bo + (size_t)(i0+r)*DH + cc*8);
    }
    auto loadKV = [&](int u){   // u = 64-key tile index, 0..31
        uint32_t st = sb + (uint32_t)(u&3)*16384u;
        for (int i = tid; i < 512; i += 256){
            int r = i>>3, cc = i&7;
            cp16(st+swz((uint32_t)(r*128 + cc*16)),
                 gkh + bo + (size_t)(u*64 + r)*DH + cc*8);
        }
        for (int i = tid; i < 512; i += 256){
            int r = i>>3, cc = i&7;
            cp16(st+8192+swz((uint32_t)(r*128 + cc*16)),
                 gvh + bo + (size_t)(u*64 + r)*DH + cc*8);
        }
        CPCOMMIT();
    };
    loadKV(0); loadKV(1); loadKV(2);   // 3 groups in flight

    float oacc[8][4] = {};
    float liacc[4] = {0.f, 0.f, 0.f, 0.f};
    const uint32_t ones = (lane < 4) ? 0x3C003C00u : 0u;
    uint32_t qf[4][4];                 // persistent Q fragments (16 regs)

    for (int t = 0; t < 32; t++){
        CPWAIT2();                       // stage t complete (<=2 groups pending)
        __syncthreads();                 // visibility + WAR for slot (t+3)&3
        if (t+3 < 32) loadKV(t+3); else CPCOMMIT();
        uint32_t st = sb + (uint32_t)(t&3)*16384u;

        if (t == 0){
            int qrow = wid*16 + (lane&15);
#pragma unroll
            for (int s = 0; s < 4; s++){
                uint32_t qo = swz((uint32_t)(qrow*128) +
                                  (uint32_t)(s*32 + ((lane>>4)&1)*16));
                ldm4(qf[s][0],qf[s][1],qf[s][2],qf[s][3], sb+65536+qo);
            }
        }

        // ---- S = Q K^T for 64 keys ----
        float sacc[8][4] = {};
#pragma unroll
        for (int s = 0; s < 4; s++){
#pragma unroll
            for (int np = 0; np < 4; np++){
                int row = np*16 + (lane&7) + ((lane&16)?8:0);
                uint32_t o = swz((uint32_t)(row*128) +
                                 (uint32_t)(s*32 + ((lane&8)?16:0)));
                uint32_t b0,b1,b2,b3;
                ldm4(b0,b1,b2,b3, st+o);
                mma16816(sacc[2*np],   qf[s][0],qf[s][1],qf[s][2],qf[s][3], b0,b1);
                mma16816(sacc[2*np+1], qf[s][0],qf[s][1],qf[s][2],qf[s][3], b2,b3);
            }
        }

        // ---- softmax (shift-free, half2) + li-MMA + PV ----
#pragma unroll
        for (int j = 0; j < 4; j++){
            uint32_t pa0 = hex2(cvt2h(sacc[2*j][1],   sacc[2*j][0]));
            uint32_t pa1 = hex2(cvt2h(sacc[2*j][3],   sacc[2*j][2]));
            uint32_t pa2 = hex2(cvt2h(sacc[2*j+1][1], sacc[2*j+1][0]));
            uint32_t pa3 = hex2(cvt2h(sacc[2*j+1][3], sacc[2*j+1][2]));

            mma16816(liacc, pa0,pa1,pa2,pa3, ones, ones);   // li += sum_k P

#pragma unroll
            for (int dp = 0; dp < 4; dp++){
                int krow = j*16 + (lane&7) + ((lane&8)?8:0);
                uint32_t db = (uint32_t)(dp*32 + ((lane&16)?16:0));
                uint32_t o = swz((uint32_t)(krow*128) + db);
                uint32_t v0,v1,v2,v3;
                ldm4t(v0,v1,v2,v3, st+8192+o);
                mma16816(oacc[2*dp],   pa0,pa1,pa2,pa3, v0,v1);
                mma16816(oacc[2*dp+1], pa0,pa1,pa2,pa3, v2,v3);
            }
        }
    }

    // li lives in column 0 of the C fragment -> lanes with lane%4==0 hold it.
    const float l0 = __shfl_sync(0xffffffffu, liacc[0], lane & ~3);
    const float l1 = __shfl_sync(0xffffffffu, liacc[2], lane & ~3);
    const float inv0 = 1.0f/l0, inv1 = 1.0f/l1;

    const int b = bh/HH, h = bh%HH;
    const int n0r = i0 + wid*16 + (lane>>2);
    const int cb  = (lane&3)*2;
    const size_t base0 = ((size_t)(b*NN + n0r))*DD + h*DH;
    const size_t base1 = base0 + (size_t)8*DD;
#pragma unroll
    for (int dt = 0; dt < 8; dt++){
        int col = dt*8 + cb;
        *(uint32_t*)(gah + base0 + col) = pk(__float2half_rn(oacc[dt][0]*inv0),
                                             __float2half_rn(oacc[dt][1]*inv0));
        *(uint32_t*)(gah + base1 + col) = pk(__float2half_rn(oacc[dt][2]*inv1),
                                             __float2half_rn(oacc[dt][3]*inv1));
    }
}

// ---------------------------------------------------------------------------
extern "C" void kernel_launch(void* const* d_in, const int* in_sizes, int n_in,
                              void* d_out, int out_size)
{
    const float* x     = (const float*)d_in[0];
    const float* w_qkv = (const float*)d_in[1];
    const float* b_qkv = (const float*)d_in[2];
    const float* w_out = (const float*)d_in[3];
    const float* b_out = (const float*)d_in[4];
    float* out = (float*)d_out;

    cudaFuncSetAttribute(qkv_tc,  cudaFuncAttributeMaxDynamicSharedMemorySize, P_SMEM);
    cudaFuncSetAttribute(out_tc,  cudaFuncAttributeMaxDynamicSharedMemorySize, P_SMEM);
    cudaFuncSetAttribute(attn_tc, cudaFuncAttributeMaxDynamicSharedMemorySize, A_SMEM);

    splitAll<<<(NX2 + 255)/256, 256>>>(x, w_qkv, w_out);

    qkv_tc<<<dim3(QKV_N/128, MMR/128), 256, P_SMEM>>>(b_qkv);
    attn_tc<<<dim3(NN/128, BB*HH), 256, A_SMEM>>>();
    out_tc<<<dim3(DD/128, MMR/128), 256, P_SMEM>>>(b_out, out);
}